// round 6
// baseline (speedup 1.0000x reference)
#include <cuda_runtime.h>
#include <cuda_bf16.h>
#include <math.h>

#define N_SRC 10000
#define N_DST 40000
#define NE    1280000
#define IN_DIM 128
#define O_DIM  300
#define FEAT   64
#define D      64

// ---------------- scratch (static device globals) ----------------
__device__ float    g_zsrc[N_SRC * D];
__device__ unsigned g_zdst_h[N_DST * 32];   // bf16x2 pairs
__device__ float    g_den[N_DST];           // partial denominators (boundary dsts)
__device__ int      g_cnt[N_DST];
__device__ int      g_start[N_DST];
__device__ int      g_cur[N_DST];
__device__ int      g_eid[NE];              // csr position -> edge id
__device__ int      g_srcs[NE];             // src id in CSR order
__device__ int      g_dsts[NE];             // dst id in CSR order
__device__ int      g_bsum[64];
__device__ int      g_bbase[64];
__device__ unsigned g_Wfb[32 * 64];         // W_feat bf16 pairs [kpair][n]
__device__ unsigned g_Wfb1[152 * 64];       // W_fc1 bf16 pairs, k padded

__device__ __forceinline__ unsigned pack_bf16(float lo, float hi) {
    unsigned u;
    asm("cvt.rn.bf16x2.f32 %0, %1, %2;" : "=r"(u) : "f"(hi), "f"(lo));
    return u;
}
__device__ __forceinline__ float2 unpack_bf16(unsigned u) {
    __nv_bfloat162 b = *(__nv_bfloat162*)&u;
    return __bfloat1622float2(b);
}

#define MMA_BF16(acc, a0, a1, a2, a3, b0, b1)                                        \
    asm volatile("mma.sync.aligned.m16n8k16.row.col.f32.bf16.bf16.f32 "              \
                 "{%0,%1,%2,%3}, {%4,%5,%6,%7}, {%8,%9}, {%0,%1,%2,%3};"             \
                 : "+f"(acc[0]), "+f"(acc[1]), "+f"(acc[2]), "+f"(acc[3])            \
                 : "r"(a0), "r"(a1), "r"(a2), "r"(a3), "r"(b0), "r"(b1))

// ---------------- K1: setup = zero cnt/den/out + pack weights ----------------
// grid: [0,157) cnt | [157,165) wfeat | [165,203) wfc1 | [203,360) den | [360,2860) out
__global__ void __launch_bounds__(256) setup_kernel(const float* __restrict__ Wfeat,
                                                    const float* __restrict__ Wfc1,
                                                    float* __restrict__ out) {
    int b = blockIdx.x;
    int tid = threadIdx.x;
    if (b < 157) {
        int i = b * 256 + tid;
        if (i < N_DST) g_cnt[i] = 0;
    } else if (b < 165) {
        int i = (b - 157) * 256 + tid;
        int kp = i >> 6, n = i & 63;
        g_Wfb[i] = pack_bf16(Wfeat[(2 * kp) * 64 + n], Wfeat[(2 * kp + 1) * 64 + n]);
    } else if (b < 203) {
        int i = (b - 165) * 256 + tid;
        if (i < 152 * 64) {
            int kp = i >> 6, n = i & 63;
            int k0 = 2 * kp, k1 = 2 * kp + 1;
            float lo = (k0 < O_DIM) ? Wfc1[k0 * 64 + n] : 0.f;
            float hi = (k1 < O_DIM) ? Wfc1[k1 * 64 + n] : 0.f;
            g_Wfb1[i] = pack_bf16(lo, hi);
        }
    } else if (b < 360) {
        int i = (b - 203) * 256 + tid;
        if (i < N_DST) g_den[i] = 0.f;
    } else {
        int i = (b - 360) * 256 + tid;   // 640000 float4 = N_DST*64/4
        ((float4*)out)[i] = make_float4(0.f, 0.f, 0.f, 0.f);
    }
}

// ---------------- K2: count || zsrc || zdst (grid-merged) ----------------
#define CB_COUNT 5000
#define CB_ZSRC  625
#define CB_ZDST  625

struct SmemZsrc { float sW[IN_DIM][D]; float sh[16][IN_DIM]; };
struct SmemZdst { unsigned sA[64][84]; unsigned sW[80][72]; };
union SmemK2 { SmemZsrc zs; SmemZdst zd; };

__device__ __forceinline__ void do_count(const int* __restrict__ dst, int b, int tid) {
    int i = b * 256 + tid;
    if (i < NE) atomicAdd(&g_cnt[dst[i]], 1);
}

__device__ __forceinline__ void do_zsrc(const float* __restrict__ h,
                                        const float* __restrict__ W,
                                        SmemZsrc& sm, int b, int tid) {
    int r0 = b * 16;
    for (int i = tid; i < IN_DIM * D / 4; i += 256)
        ((float4*)&sm.sW[0][0])[i] = ((const float4*)W)[i];
    for (int i = tid; i < 16 * IN_DIM / 4; i += 256)
        ((float4*)&sm.sh[0][0])[i] = ((const float4*)(h + (size_t)r0 * IN_DIM))[i];
    __syncthreads();
    int d4 = (tid & 15) * 4;
    int r  = tid >> 4;
    float a0 = 0.f, a1 = 0.f, a2 = 0.f, a3 = 0.f;
#pragma unroll 8
    for (int k = 0; k < IN_DIM; k++) {
        float hv = sm.sh[r][k];
        float4 w = *(const float4*)&sm.sW[k][d4];
        a0 += hv * w.x; a1 += hv * w.y; a2 += hv * w.z; a3 += hv * w.w;
    }
    *(float4*)&g_zsrc[(size_t)(r0 + r) * D + d4] = make_float4(a0, a1, a2, a3);
}

__device__ __forceinline__ void do_zdst(const float* __restrict__ o,
                                        SmemZdst& sm, int b, int tid) {
    int lane = tid & 31, warp = tid >> 5;
    int r0 = b * 64;
    int g = lane >> 2, qp = lane & 3;
    int mt = warp & 3;
    int nh = warp >> 2;

    float acc[4][4];
#pragma unroll
    for (int nt = 0; nt < 4; nt++)
        acc[nt][0] = acc[nt][1] = acc[nt][2] = acc[nt][3] = 0.f;

    for (int c = 0; c < 2; c++) {
        int kp0 = c * 80;
        __syncthreads();
        for (int i = tid; i < 64 * 80; i += 256) {
            int row = i / 80, kp = i % 80;
            int gkp = kp0 + kp;
            float lo = 0.f, hi = 0.f;
            if (gkp < 150) {
                float2 v = *(const float2*)&o[(size_t)(r0 + row) * O_DIM + gkp * 2];
                lo = v.x; hi = v.y;
            }
            sm.sA[row][kp] = pack_bf16(lo, hi);
        }
        int npair = c ? 72 : 80;
        for (int i = tid; i < npair * 64; i += 256) {
            int kp = i >> 6, n = i & 63;
            sm.sW[kp][n] = g_Wfb1[(kp0 + kp) * 64 + n];
        }
        __syncthreads();
        int nkt = c ? 9 : 10;
        for (int lt = 0; lt < nkt; lt++) {
            unsigned a0 = sm.sA[mt * 16 + g][lt * 8 + qp];
            unsigned a1 = sm.sA[mt * 16 + g + 8][lt * 8 + qp];
            unsigned a2 = sm.sA[mt * 16 + g][lt * 8 + qp + 4];
            unsigned a3 = sm.sA[mt * 16 + g + 8][lt * 8 + qp + 4];
#pragma unroll
            for (int nt = 0; nt < 4; nt++) {
                int nn = (nh * 4 + nt) * 8 + g;
                unsigned b0 = sm.sW[lt * 8 + qp][nn];
                unsigned b1 = sm.sW[lt * 8 + qp + 4][nn];
                MMA_BF16(acc[nt], a0, a1, a2, a3, b0, b1);
            }
        }
    }
    int row0 = r0 + mt * 16 + g;
#pragma unroll
    for (int nt = 0; nt < 4; nt++) {
        int pair = (nh * 4 + nt) * 4 + qp;
        g_zdst_h[(size_t)row0 * 32 + pair]       = pack_bf16(acc[nt][0], acc[nt][1]);
        g_zdst_h[(size_t)(row0 + 8) * 32 + pair] = pack_bf16(acc[nt][2], acc[nt][3]);
    }
}

__global__ void __launch_bounds__(256) fused_k2_kernel(const int* __restrict__ edst,
                                                       const float* __restrict__ h,
                                                       const float* __restrict__ W_fc,
                                                       const float* __restrict__ o) {
    __shared__ SmemK2 sm;
    int b = blockIdx.x, tid = threadIdx.x;
    if (b < CB_COUNT) {
        do_count(edst, b, tid);
    } else if (b < CB_COUNT + CB_ZSRC) {
        do_zsrc(h, W_fc, sm.zs, b - CB_COUNT, tid);
    } else {
        do_zdst(o, sm.zd, b - CB_COUNT - CB_ZSRC, tid);
    }
}

// ---------------- CSR scans + fill ----------------
__global__ void __launch_bounds__(1024) scan1_kernel() {
    __shared__ int wsum[32];
    __shared__ int wpre[32];
    int tid = threadIdx.x, lane = tid & 31, wid = tid >> 5;
    int i = blockIdx.x * 1024 + tid;
    int v = (i < N_DST) ? g_cnt[i] : 0;
    int x = v;
#pragma unroll
    for (int off = 1; off < 32; off <<= 1) {
        int t = __shfl_up_sync(0xffffffffu, x, off);
        if (lane >= off) x += t;
    }
    if (lane == 31) wsum[wid] = x;
    __syncthreads();
    if (wid == 0) {
        int s = wsum[lane];
#pragma unroll
        for (int off = 1; off < 32; off <<= 1) {
            int t = __shfl_up_sync(0xffffffffu, s, off);
            if (lane >= off) s += t;
        }
        wpre[lane] = s;
    }
    __syncthreads();
    int base = wid ? wpre[wid - 1] : 0;
    if (i < N_DST) g_start[i] = base + x - v;
    if (tid == 0) g_bsum[blockIdx.x] = wpre[31];
}
__global__ void scan2_kernel() {
    __shared__ int s[64];
    int tid = threadIdx.x;
    s[tid] = (tid < 40) ? g_bsum[tid] : 0;
    __syncthreads();
#pragma unroll
    for (int off = 1; off < 64; off <<= 1) {
        int t = (tid >= off) ? s[tid - off] : 0;
        __syncthreads();
        s[tid] += t;
        __syncthreads();
    }
    if (tid < 40) g_bbase[tid] = s[tid] - g_bsum[tid];
}
__global__ void __launch_bounds__(1024) scan3_kernel() {
    int i = blockIdx.x * 1024 + threadIdx.x;
    if (i < N_DST) {
        int st = g_start[i] + g_bbase[blockIdx.x];
        g_start[i] = st;
        g_cur[i]   = st;
    }
}
__global__ void fill_kernel(const int* __restrict__ dst, const int* __restrict__ src) {
    int i = blockIdx.x * 256 + threadIdx.x;
    if (i < NE) {
        int d = dst[i];
        int p = atomicAdd(&g_cur[d], 1);
        g_eid[p]  = i;
        g_srcs[p] = src[i];
        g_dsts[p] = d;
    }
}

// ---------------- fused edge logits + softmax + aggregation ----------------
// 128 CSR positions / block, 8 warps x 16 edges; dynamic smem
struct SmemEdge {
    unsigned sT[128][36];   // tfidf bf16 pairs
    unsigned sW[32][72];    // W_feat bf16 pairs
    float    sZf[128][68];  // src z rows f32, pitch 68 (conflict-free)
    float    sWt[128];      // exp(logit)
    int      sS[128];       // src ids (csr order)
    int      sD[128];       // dst ids (csr order)
    int      sE[128];       // edge ids
    int      sRun[130];
    int      sNr;
    int      sPrevDst, sNextDst;
};

__global__ void __launch_bounds__(256) edge_kernel(const float* __restrict__ tfidf,
                                                   const float* __restrict__ bfeat,
                                                   const float* __restrict__ Wattn,
                                                   float* __restrict__ out) {
    extern __shared__ char smem_raw[];
    SmemEdge& sm = *(SmemEdge*)smem_raw;
    int tid  = threadIdx.x;
    int base = blockIdx.x * 128;

    if (tid < 128) {
        sm.sE[tid] = g_eid[base + tid];
        sm.sS[tid] = g_srcs[base + tid];
        sm.sD[tid] = g_dsts[base + tid];
    }
    if (tid == 254) sm.sPrevDst = (base > 0) ? g_dsts[base - 1] : -1;
    if (tid == 255) sm.sNextDst = (base + 128 < NE) ? g_dsts[base + 128] : -1;
    for (int i = tid; i < 32 * 64; i += 256)
        sm.sW[i >> 6][i & 63] = g_Wfb[i];
    __syncthreads();

    // stage tfidf rows (bf16) + src z rows (f32)
    for (int i = tid; i < 128 * 32; i += 256) {
        int row = i >> 5, kp = i & 31;
        float2 v = *(const float2*)&tfidf[(size_t)sm.sE[row] * FEAT + kp * 2];
        sm.sT[row][kp] = pack_bf16(v.x, v.y);
    }
    for (int i = tid; i < 128 * 16; i += 256) {
        int end = i >> 4, c = i & 15;
        float4 v = *(const float4*)&g_zsrc[(size_t)sm.sS[end] * D + c * 4];
        *(float4*)&sm.sZf[end][c * 4] = v;
    }
    __syncthreads();

    int lane = tid & 31, warp = tid >> 5;
    int g = lane >> 2, qp = lane & 3;
    int wb = warp * 16;

    float acc[8][4];
#pragma unroll
    for (int nt = 0; nt < 8; nt++)
        acc[nt][0] = acc[nt][1] = acc[nt][2] = acc[nt][3] = 0.f;

#pragma unroll
    for (int kt = 0; kt < 4; kt++) {
        unsigned a0 = sm.sT[wb + g][kt * 8 + qp];
        unsigned a1 = sm.sT[wb + g + 8][kt * 8 + qp];
        unsigned a2 = sm.sT[wb + g][kt * 8 + qp + 4];
        unsigned a3 = sm.sT[wb + g + 8][kt * 8 + qp + 4];
#pragma unroll
        for (int nt = 0; nt < 8; nt++) {
            unsigned b0 = sm.sW[kt * 8 + qp][nt * 8 + g];
            unsigned b1 = sm.sW[kt * 8 + qp + 4][nt * 8 + g];
            MMA_BF16(acc[nt], a0, a1, a2, a3, b0, b1);
        }
    }

    // epilogue: + z_src(f32 smem) + z_dst(bf16 global) + bias, leaky, dot W_attn
    int d0 = sm.sD[wb + g], d1 = sm.sD[wb + g + 8];
    float p0 = 0.f, p1 = 0.f;
#pragma unroll
    for (int nt = 0; nt < 8; nt++) {
        int col  = nt * 8 + qp * 2;
        int pair = nt * 4 + qp;
        float2 bf  = *(const float2*)&bfeat[col];
        float2 wa  = *(const float2*)&Wattn[col];
        float2 zs0 = *(const float2*)&sm.sZf[wb + g][col];
        float2 zs1 = *(const float2*)&sm.sZf[wb + g + 8][col];
        float2 zd0 = unpack_bf16(g_zdst_h[(size_t)d0 * 32 + pair]);
        float2 zd1 = unpack_bf16(g_zdst_h[(size_t)d1 * 32 + pair]);
        float v;
        v = acc[nt][0] + zs0.x + zd0.x + bf.x; v = v > 0.f ? v : 0.01f * v; p0 += v * wa.x;
        v = acc[nt][1] + zs0.y + zd0.y + bf.y; v = v > 0.f ? v : 0.01f * v; p0 += v * wa.y;
        v = acc[nt][2] + zs1.x + zd1.x + bf.x; v = v > 0.f ? v : 0.01f * v; p1 += v * wa.x;
        v = acc[nt][3] + zs1.y + zd1.y + bf.y; v = v > 0.f ? v : 0.01f * v; p1 += v * wa.y;
    }
    p0 += __shfl_xor_sync(0xffffffffu, p0, 1);
    p0 += __shfl_xor_sync(0xffffffffu, p0, 2);
    p1 += __shfl_xor_sync(0xffffffffu, p1, 1);
    p1 += __shfl_xor_sync(0xffffffffu, p1, 2);
    if (qp == 0) {
        sm.sWt[wb + g]     = __expf(p0);   // no-max softmax: logits are O(1)
        sm.sWt[wb + g + 8] = __expf(p1);
    }

    // ---- run detection (warp 0) ----
    if (warp == 0) {
        int runbase = 0;
        __syncwarp();
    }
    __syncthreads();
    if (warp == 0) {
        int runbase = 0;
        for (int b4 = 0; b4 < 128; b4 += 32) {
            int t = b4 + lane;
            bool flag = (t == 0) || (sm.sD[t] != sm.sD[t - 1]);
            unsigned bal = __ballot_sync(0xffffffffu, flag);
            int idx = runbase + __popc(bal & ((1u << lane) - 1));
            if (flag) sm.sRun[idx] = t;
            runbase += __popc(bal);
        }
        if (lane == 0) {
            sm.sNr = runbase;
            sm.sRun[runbase] = 128;
        }
    }
    __syncthreads();

    // ---- segment aggregation: warp per run, lane owns 2 output cols ----
    int nr = sm.sNr;
    for (int r = warp; r < nr; r += 8) {
        int s = sm.sRun[r], e = sm.sRun[r + 1];
        int dst = sm.sD[s];
        float den = 0.f, ax = 0.f, ay = 0.f;
        for (int j = s; j < e; j++) {
            float wv = sm.sWt[j];
            float2 z = *(const float2*)&sm.sZf[j][2 * lane];
            den += wv;
            ax += wv * z.x;
            ay += wv * z.y;
        }
        bool open_lo = (s == 0)   && (sm.sPrevDst == dst);
        bool open_hi = (e == 128) && (sm.sNextDst == dst);
        float* op = &out[(size_t)dst * D + 2 * lane];
        if (!open_lo && !open_hi) {
            float inv = 1.0f / fmaxf(den, 1e-9f);
            *(float2*)op = make_float2(ax * inv, ay * inv);
        } else {
            atomicAdd(op, ax);
            atomicAdd(op + 1, ay);
            if (lane == 0) atomicAdd(&g_den[dst], den);
        }
    }
}

// ---------------- normalize boundary dsts ----------------
__global__ void __launch_bounds__(256) norm_kernel(float* __restrict__ out) {
    int w    = (blockIdx.x * blockDim.x + threadIdx.x) >> 5;
    int lane = threadIdx.x & 31;
    if (w >= N_DST) return;
    float den = g_den[w];
    if (den != 0.f) {
        float inv = 1.0f / fmaxf(den, 1e-9f);
        float2* p = (float2*)&out[(size_t)w * D + 2 * lane];
        float2 v = *p;
        *p = make_float2(v.x * inv, v.y * inv);
    }
}

// ---------------- launch ----------------
extern "C" void kernel_launch(void* const* d_in, const int* in_sizes, int n_in,
                              void* d_out, int out_size) {
    const float* h      = (const float*)d_in[0];
    const float* o      = (const float*)d_in[1];
    const float* tfidf  = (const float*)d_in[2];
    const float* W_fc   = (const float*)d_in[3];
    const float* W_fc1  = (const float*)d_in[4];
    const float* W_feat = (const float*)d_in[5];
    const float* b_feat = (const float*)d_in[6];
    const float* W_attn = (const float*)d_in[7];
    const int* esrc     = (const int*)d_in[8];
    const int* edst     = (const int*)d_in[9];
    float* out = (float*)d_out;

    static bool attr_set = false;
    if (!attr_set) {
        cudaFuncSetAttribute(edge_kernel, cudaFuncAttributeMaxDynamicSharedMemorySize,
                             (int)sizeof(SmemEdge));
        attr_set = true;
    }

    setup_kernel<<<2860, 256>>>(W_feat, W_fc1, out);
    fused_k2_kernel<<<CB_COUNT + CB_ZSRC + CB_ZDST, 256>>>(edst, h, W_fc, o);
    scan1_kernel<<<40, 1024>>>();
    scan2_kernel<<<1, 64>>>();
    scan3_kernel<<<40, 1024>>>();
    fill_kernel<<<(NE + 255) / 256, 256>>>(edst, esrc);
    edge_kernel<<<NE / 128, 256, sizeof(SmemEdge)>>>(tfidf, b_feat, W_attn, out);
    norm_kernel<<<(N_DST * 32 + 255) / 256, 256>>>(out);
}

// round 7
// speedup vs baseline: 1.2336x; 1.2336x over previous
#include <cuda_runtime.h>
#include <cuda_bf16.h>
#include <math.h>

#define N_SRC 10000
#define N_DST 40000
#define NE    1280000
#define IN_DIM 128
#define O_DIM  300
#define FEAT   64
#define D      64

// ---------------- scratch (static device globals) ----------------
__device__ float    g_zsrc[N_SRC * D];
__device__ unsigned g_zsrc_h[N_SRC * 32];   // bf16x2 pairs
__device__ unsigned g_zdst_h[N_DST * 32];   // bf16x2 pairs
__device__ float    g_e[NE];                // exp(logit) in CSR order
__device__ int      g_cnt[N_DST];
__device__ int      g_start[N_DST];
__device__ int      g_cur[N_DST];
__device__ int      g_eid[NE];              // csr position -> edge id
__device__ int      g_srcs[NE];             // src id in CSR order
__device__ int      g_dsts[NE];             // dst id in CSR order
__device__ int      g_bsum[64];
__device__ int      g_bbase[64];
__device__ unsigned g_Wfb[32 * 64];         // W_feat bf16 pairs [kpair][n]
__device__ unsigned g_Wfb1[152 * 64];       // W_fc1 bf16 pairs, k padded

__device__ __forceinline__ unsigned pack_bf16(float lo, float hi) {
    unsigned u;
    asm("cvt.rn.bf16x2.f32 %0, %1, %2;" : "=r"(u) : "f"(hi), "f"(lo));
    return u;
}
__device__ __forceinline__ float2 unpack_bf16(unsigned u) {
    __nv_bfloat162 b = *(__nv_bfloat162*)&u;
    return __bfloat1622float2(b);
}

#define MMA_BF16(acc, a0, a1, a2, a3, b0, b1)                                        \
    asm volatile("mma.sync.aligned.m16n8k16.row.col.f32.bf16.bf16.f32 "              \
                 "{%0,%1,%2,%3}, {%4,%5,%6,%7}, {%8,%9}, {%0,%1,%2,%3};"             \
                 : "+f"(acc[0]), "+f"(acc[1]), "+f"(acc[2]), "+f"(acc[3])            \
                 : "r"(a0), "r"(a1), "r"(a2), "r"(a3), "r"(b0), "r"(b1))

// ---------------- K1: setup = zero cnt + pack weights ----------------
__global__ void __launch_bounds__(256) setup_kernel(const float* __restrict__ Wfeat,
                                                    const float* __restrict__ Wfc1) {
    int b = blockIdx.x;
    int tid = threadIdx.x;
    if (b < 157) {
        int i = b * 256 + tid;
        if (i < N_DST) g_cnt[i] = 0;
    } else if (b < 165) {
        int i = (b - 157) * 256 + tid;
        int kp = i >> 6, n = i & 63;
        g_Wfb[i] = pack_bf16(Wfeat[(2 * kp) * 64 + n], Wfeat[(2 * kp + 1) * 64 + n]);
    } else {
        int i = (b - 165) * 256 + tid;
        if (i < 152 * 64) {
            int kp = i >> 6, n = i & 63;
            int k0 = 2 * kp, k1 = 2 * kp + 1;
            float lo = (k0 < O_DIM) ? Wfc1[k0 * 64 + n] : 0.f;
            float hi = (k1 < O_DIM) ? Wfc1[k1 * 64 + n] : 0.f;
            g_Wfb1[i] = pack_bf16(lo, hi);
        }
    }
}

// ---------------- work pieces ----------------
struct SmemZsrc { float sW[IN_DIM][D]; float sh[16][IN_DIM]; };
struct SmemZdst { unsigned sA[64][84]; unsigned sW[80][72]; };

__device__ __forceinline__ void do_zsrc(const float* __restrict__ h,
                                        const float* __restrict__ W,
                                        SmemZsrc& sm, int b, int tid) {
    int r0 = b * 16;
    for (int i = tid; i < IN_DIM * D / 4; i += 256)
        ((float4*)&sm.sW[0][0])[i] = ((const float4*)W)[i];
    for (int i = tid; i < 16 * IN_DIM / 4; i += 256)
        ((float4*)&sm.sh[0][0])[i] = ((const float4*)(h + (size_t)r0 * IN_DIM))[i];
    __syncthreads();
    int d4 = (tid & 15) * 4;
    int r  = tid >> 4;
    float a0 = 0.f, a1 = 0.f, a2 = 0.f, a3 = 0.f;
#pragma unroll 8
    for (int k = 0; k < IN_DIM; k++) {
        float hv = sm.sh[r][k];
        float4 w = *(const float4*)&sm.sW[k][d4];
        a0 += hv * w.x; a1 += hv * w.y; a2 += hv * w.z; a3 += hv * w.w;
    }
    int node = r0 + r;
    *(float4*)&g_zsrc[(size_t)node * D + d4] = make_float4(a0, a1, a2, a3);
    *(uint2*)&g_zsrc_h[(size_t)node * 32 + d4 / 2] =
        make_uint2(pack_bf16(a0, a1), pack_bf16(a2, a3));
}

__device__ __forceinline__ void do_zdst(const float* __restrict__ o,
                                        SmemZdst& sm, int b, int tid) {
    int lane = tid & 31, warp = tid >> 5;
    int r0 = b * 64;
    int g = lane >> 2, qp = lane & 3;
    int mt = warp & 3;
    int nh = warp >> 2;

    float acc[4][4];
#pragma unroll
    for (int nt = 0; nt < 4; nt++)
        acc[nt][0] = acc[nt][1] = acc[nt][2] = acc[nt][3] = 0.f;

    for (int c = 0; c < 2; c++) {
        int kp0 = c * 80;
        __syncthreads();
        for (int i = tid; i < 64 * 80; i += 256) {
            int row = i / 80, kp = i % 80;
            int gkp = kp0 + kp;
            float lo = 0.f, hi = 0.f;
            if (gkp < 150) {
                float2 v = *(const float2*)&o[(size_t)(r0 + row) * O_DIM + gkp * 2];
                lo = v.x; hi = v.y;
            }
            sm.sA[row][kp] = pack_bf16(lo, hi);
        }
        int npair = c ? 72 : 80;
        for (int i = tid; i < npair * 64; i += 256) {
            int kp = i >> 6, n = i & 63;
            sm.sW[kp][n] = g_Wfb1[(kp0 + kp) * 64 + n];
        }
        __syncthreads();
        int nkt = c ? 9 : 10;
        for (int lt = 0; lt < nkt; lt++) {
            unsigned a0 = sm.sA[mt * 16 + g][lt * 8 + qp];
            unsigned a1 = sm.sA[mt * 16 + g + 8][lt * 8 + qp];
            unsigned a2 = sm.sA[mt * 16 + g][lt * 8 + qp + 4];
            unsigned a3 = sm.sA[mt * 16 + g + 8][lt * 8 + qp + 4];
#pragma unroll
            for (int nt = 0; nt < 4; nt++) {
                int nn = (nh * 4 + nt) * 8 + g;
                unsigned b0 = sm.sW[lt * 8 + qp][nn];
                unsigned b1 = sm.sW[lt * 8 + qp + 4][nn];
                MMA_BF16(acc[nt], a0, a1, a2, a3, b0, b1);
            }
        }
    }
    int row0 = r0 + mt * 16 + g;
#pragma unroll
    for (int nt = 0; nt < 4; nt++) {
        int pair = (nh * 4 + nt) * 4 + qp;
        g_zdst_h[(size_t)row0 * 32 + pair]       = pack_bf16(acc[nt][0], acc[nt][1]);
        g_zdst_h[(size_t)(row0 + 8) * 32 + pair] = pack_bf16(acc[nt][2], acc[nt][3]);
    }
}

// ---------------- K2: count || zsrc ----------------
__global__ void __launch_bounds__(256) count_zsrc_kernel(const int* __restrict__ edst,
                                                         const float* __restrict__ h,
                                                         const float* __restrict__ W_fc) {
    __shared__ SmemZsrc sm;
    int b = blockIdx.x, tid = threadIdx.x;
    if (b < 5000) {
        int i = b * 256 + tid;
        if (i < NE) atomicAdd(&g_cnt[edst[i]], 1);
    } else {
        do_zsrc(h, W_fc, sm, b - 5000, tid);
    }
}

// ---------------- CSR scans ----------------
__global__ void __launch_bounds__(1024) scan1_kernel() {
    __shared__ int wsum[32];
    __shared__ int wpre[32];
    int tid = threadIdx.x, lane = tid & 31, wid = tid >> 5;
    int i = blockIdx.x * 1024 + tid;
    int v = (i < N_DST) ? g_cnt[i] : 0;
    int x = v;
#pragma unroll
    for (int off = 1; off < 32; off <<= 1) {
        int t = __shfl_up_sync(0xffffffffu, x, off);
        if (lane >= off) x += t;
    }
    if (lane == 31) wsum[wid] = x;
    __syncthreads();
    if (wid == 0) {
        int s = wsum[lane];
#pragma unroll
        for (int off = 1; off < 32; off <<= 1) {
            int t = __shfl_up_sync(0xffffffffu, s, off);
            if (lane >= off) s += t;
        }
        wpre[lane] = s;
    }
    __syncthreads();
    int base = wid ? wpre[wid - 1] : 0;
    if (i < N_DST) g_start[i] = base + x - v;
    if (tid == 0) g_bsum[blockIdx.x] = wpre[31];
}
__global__ void scan2_kernel() {
    __shared__ int s[64];
    int tid = threadIdx.x;
    s[tid] = (tid < 40) ? g_bsum[tid] : 0;
    __syncthreads();
#pragma unroll
    for (int off = 1; off < 64; off <<= 1) {
        int t = (tid >= off) ? s[tid - off] : 0;
        __syncthreads();
        s[tid] += t;
        __syncthreads();
    }
    if (tid < 40) g_bbase[tid] = s[tid] - g_bsum[tid];
}
__global__ void __launch_bounds__(1024) scan3_kernel() {
    int i = blockIdx.x * 1024 + threadIdx.x;
    if (i < N_DST) {
        int st = g_start[i] + g_bbase[blockIdx.x];
        g_start[i] = st;
        g_cur[i]   = st;
    }
}

// ---------------- K4: fill || zdst ----------------
__global__ void __launch_bounds__(256) fill_zdst_kernel(const int* __restrict__ edst,
                                                        const int* __restrict__ esrc,
                                                        const float* __restrict__ o) {
    __shared__ SmemZdst sm;
    int b = blockIdx.x, tid = threadIdx.x;
    if (b < 5000) {
        int i = b * 256 + tid;
        if (i < NE) {
            int d = edst[i];
            int p = atomicAdd(&g_cur[d], 1);
            g_eid[p]  = i;
            g_srcs[p] = esrc[i];
            g_dsts[p] = d;
        }
    } else {
        do_zdst(o, sm, b - 5000, tid);
    }
}

// ---------------- edge logits in CSR order (bf16 MMA, smem z staging) ----------------
__global__ void __launch_bounds__(256) edge_kernel(const float* __restrict__ tfidf,
                                                   const float* __restrict__ bfeat,
                                                   const float* __restrict__ Wattn) {
    __shared__ unsigned sT[128][36];  // [edge][kpair]
    __shared__ unsigned sW[32][72];   // [kpair][n]
    __shared__ unsigned sZ[128][36];  // src z shadow rows (bf16x2), cols 0..31 used
    __shared__ int sE[128];
    __shared__ int sS[128];
    __shared__ int sD[128];
    int tid  = threadIdx.x;
    int base = blockIdx.x * 128;

    if (tid < 128) {
        sE[tid] = g_eid[base + tid];
        sS[tid] = g_srcs[base + tid];
        sD[tid] = g_dsts[base + tid];
    }
    for (int i = tid; i < 32 * 64; i += 256)
        sW[i >> 6][i & 63] = g_Wfb[i];
    __syncthreads();

    for (int i = tid; i < 128 * 32; i += 256) {
        int row = i >> 5, kp = i & 31;
        float2 v = *(const float2*)&tfidf[(size_t)sE[row] * FEAT + kp * 2];
        sT[row][kp] = pack_bf16(v.x, v.y);
    }
    for (int i = tid; i < 128 * 8; i += 256) {
        int end = i >> 3, c = i & 7;
        uint4 v = *(const uint4*)&g_zsrc_h[(size_t)sS[end] * 32 + c * 4];
        *(uint4*)&sZ[end][c * 4] = v;
    }
    __syncthreads();

    int lane = tid & 31, warp = tid >> 5;
    int g = lane >> 2, qp = lane & 3;
    int wb = warp * 16;

    float acc[8][4];
#pragma unroll
    for (int nt = 0; nt < 8; nt++)
        acc[nt][0] = acc[nt][1] = acc[nt][2] = acc[nt][3] = 0.f;

#pragma unroll
    for (int kt = 0; kt < 4; kt++) {
        unsigned a0 = sT[wb + g][kt * 8 + qp];
        unsigned a1 = sT[wb + g + 8][kt * 8 + qp];
        unsigned a2 = sT[wb + g][kt * 8 + qp + 4];
        unsigned a3 = sT[wb + g + 8][kt * 8 + qp + 4];
#pragma unroll
        for (int nt = 0; nt < 8; nt++) {
            unsigned b0 = sW[kt * 8 + qp][nt * 8 + g];
            unsigned b1 = sW[kt * 8 + qp + 4][nt * 8 + g];
            MMA_BF16(acc[nt], a0, a1, a2, a3, b0, b1);
        }
    }

    // epilogue
    int p0i = base + wb + g;
    int p1i = p0i + 8;
    int d0 = sD[wb + g], d1 = sD[wb + g + 8];
    float p0 = 0.f, p1 = 0.f;
#pragma unroll
    for (int nt = 0; nt < 8; nt++) {
        int col  = nt * 8 + qp * 2;
        int pair = nt * 4 + qp;
        float2 bf  = *(const float2*)&bfeat[col];
        float2 wa  = *(const float2*)&Wattn[col];
        float2 zs0 = unpack_bf16(sZ[wb + g][pair]);
        float2 zs1 = unpack_bf16(sZ[wb + g + 8][pair]);
        float2 zd0 = unpack_bf16(g_zdst_h[(size_t)d0 * 32 + pair]);
        float2 zd1 = unpack_bf16(g_zdst_h[(size_t)d1 * 32 + pair]);
        float v;
        v = acc[nt][0] + zs0.x + zd0.x + bf.x; v = v > 0.f ? v : 0.01f * v; p0 += v * wa.x;
        v = acc[nt][1] + zs0.y + zd0.y + bf.y; v = v > 0.f ? v : 0.01f * v; p0 += v * wa.y;
        v = acc[nt][2] + zs1.x + zd1.x + bf.x; v = v > 0.f ? v : 0.01f * v; p1 += v * wa.x;
        v = acc[nt][3] + zs1.y + zd1.y + bf.y; v = v > 0.f ? v : 0.01f * v; p1 += v * wa.y;
    }
    p0 += __shfl_xor_sync(0xffffffffu, p0, 1);
    p0 += __shfl_xor_sync(0xffffffffu, p0, 2);
    p1 += __shfl_xor_sync(0xffffffffu, p1, 1);
    p1 += __shfl_xor_sync(0xffffffffu, p1, 2);
    if (qp == 0) {
        g_e[p0i] = __expf(p0);   // no-max softmax: logits are O(1)
        g_e[p1i] = __expf(p1);
    }
}

// ---------------- single-pass softmax + aggregation (warp per dst) ----------------
// 2 edges per iteration: half-warps own one edge each, float4 cols
__global__ void __launch_bounds__(256) agg_kernel(float* __restrict__ out) {
    int w    = (blockIdx.x * blockDim.x + threadIdx.x) >> 5;
    int lane = threadIdx.x & 31;
    if (w >= N_DST) return;
    int start = g_start[w];
    int deg   = g_cnt[w];
    int half  = lane >> 4;      // 0: even edges, 1: odd edges
    int li    = lane & 15;      // owns cols 4*li .. 4*li+3

    float denom = 0.f;
    float a0 = 0.f, a1 = 0.f, a2 = 0.f, a3 = 0.f;
    for (int j0 = 0; j0 < deg; j0 += 32) {
        int j = j0 + lane;
        float we = 0.f;
        int s = 0;
        if (j < deg) {
            we = g_e[start + j];      // already exp()
            s  = g_srcs[start + j];
        }
        denom += we;
        int n = min(32, deg - j0);
        for (int k = 0; k < n; k += 2) {
            int idx = k + half;
            float a = __shfl_sync(0xffffffffu, we, idx & 31);
            int  ss = __shfl_sync(0xffffffffu, s, idx & 31);
            if (idx >= n) a = 0.f;    // odd tail: invalid lanes had s=0, safe index
            float4 z = *(const float4*)&g_zsrc[(size_t)ss * D + 4 * li];
            a0 += a * z.x; a1 += a * z.y; a2 += a * z.z; a3 += a * z.w;
        }
    }
    // merge even/odd halves
    a0 += __shfl_xor_sync(0xffffffffu, a0, 16);
    a1 += __shfl_xor_sync(0xffffffffu, a1, 16);
    a2 += __shfl_xor_sync(0xffffffffu, a2, 16);
    a3 += __shfl_xor_sync(0xffffffffu, a3, 16);
#pragma unroll
    for (int off = 16; off; off >>= 1) denom += __shfl_xor_sync(0xffffffffu, denom, off);
    float inv = 1.0f / fmaxf(denom, 1e-9f);
    if (lane < 16)
        *(float4*)&out[(size_t)w * D + 4 * li] =
            make_float4(a0 * inv, a1 * inv, a2 * inv, a3 * inv);
}

// ---------------- launch ----------------
extern "C" void kernel_launch(void* const* d_in, const int* in_sizes, int n_in,
                              void* d_out, int out_size) {
    const float* h      = (const float*)d_in[0];
    const float* o      = (const float*)d_in[1];
    const float* tfidf  = (const float*)d_in[2];
    const float* W_fc   = (const float*)d_in[3];
    const float* W_fc1  = (const float*)d_in[4];
    const float* W_feat = (const float*)d_in[5];
    const float* b_feat = (const float*)d_in[6];
    const float* W_attn = (const float*)d_in[7];
    const int* esrc     = (const int*)d_in[8];
    const int* edst     = (const int*)d_in[9];
    float* out = (float*)d_out;

    setup_kernel<<<203, 256>>>(W_feat, W_fc1);
    count_zsrc_kernel<<<5000 + 625, 256>>>(edst, h, W_fc);
    scan1_kernel<<<40, 1024>>>();
    scan2_kernel<<<1, 64>>>();
    scan3_kernel<<<40, 1024>>>();
    fill_zdst_kernel<<<5000 + 625, 256>>>(edst, esrc, o);
    edge_kernel<<<NE / 128, 256>>>(tfidf, b_feat, W_attn);
    agg_kernel<<<(N_DST * 32 + 255) / 256, 256>>>(out);
}